// round 14
// baseline (speedup 1.0000x reference)
#include <cuda_runtime.h>
#include <cstdint>

#define D 64
#define MAXN 100000
#define MAXE 1600000
#define WAVE 128
#define NT 256

#define ENT 288
#define ENW 9
#define EGRID 152
#define RING 8          // ring slots (power of 2)
#define LWS 68          // padded row stride for sLW
#define EOFFW 76        // per-warp offset-table entries (>= npw+1 = 75)

// Scratch (static device globals; no runtime allocation allowed)
__device__ float g_h[(size_t)MAXN * D];   // h = node_h @ W_fc^T
__device__ int   g_deg[MAXN];
__device__ int   g_off[MAXN + 1];
__device__ int   g_cur[MAXN];
__device__ int   g_bsum[128];
__device__ int2  g_pes[MAXE];             // permuted (edge_idx, src)

typedef unsigned long long ull;

__device__ __forceinline__ ull fma2(ull a, ull b, ull c) {
    ull d;
    asm("fma.rn.f32x2 %0, %1, %2, %3;" : "=l"(d) : "l"(a), "l"(b), "l"(c));
    return d;
}
__device__ __forceinline__ float2 unpack2(ull v) {
    float2 r;
    asm("mov.b64 {%0, %1}, %2;" : "=f"(r.x), "=f"(r.y) : "l"(v));
    return r;
}
__device__ __forceinline__ void cp16(void* s, const void* g) {
    unsigned a = (unsigned)__cvta_generic_to_shared(s);
    asm volatile("cp.async.cg.shared.global [%0], [%1], 16;" :: "r"(a), "l"(g));
}
__device__ __forceinline__ void cp8(void* s, const void* g) {
    unsigned a = (unsigned)__cvta_generic_to_shared(s);
    asm volatile("cp.async.ca.shared.global [%0], [%1], 8;" :: "r"(a), "l"(g));
}
#define CP_COMMIT() asm volatile("cp.async.commit_group;" ::: "memory")
#define CP_WAIT1()  asm volatile("cp.async.wait_group 1;" ::: "memory")
#define CP_WAIT0()  asm volatile("cp.async.wait_group 0;" ::: "memory")
#define CP_WAIT3()  asm volatile("cp.async.wait_group 3;" ::: "memory")

// ---------------------------------------------------------------------------
__global__ void k_zero(int n4) {
    int i = blockIdx.x * blockDim.x + threadIdx.x;
    if (i < n4) ((int4*)g_deg)[i] = make_int4(0, 0, 0, 0);
}

__global__ void k_hist(const int* __restrict__ dst, int E) {
    int i = blockIdx.x * blockDim.x + threadIdx.x;
    if (i < E) atomicAdd(&g_deg[dst[i]], 1);
}

__global__ void k_scan1(int N) {
    __shared__ int s[1024];
    int t = threadIdx.x;
    int i = blockIdx.x * 1024 + t;
    int v = (i < N) ? g_deg[i] : 0;
    s[t] = v; __syncthreads();
#pragma unroll
    for (int d = 1; d < 1024; d <<= 1) {
        int u = (t >= d) ? s[t - d] : 0;
        __syncthreads();
        s[t] += u;
        __syncthreads();
    }
    if (i < N) g_off[i] = s[t] - v;
    if (t == 1023) g_bsum[blockIdx.x] = s[t];
}

__global__ void k_scan2(int nb, int N) {
    __shared__ int s[128];
    int t = threadIdx.x;
    int v = (t < nb) ? g_bsum[t] : 0;
    s[t] = v; __syncthreads();
#pragma unroll
    for (int d = 1; d < 128; d <<= 1) {
        int u = (t >= d) ? s[t - d] : 0;
        __syncthreads();
        s[t] += u;
        __syncthreads();
    }
    if (t < nb) g_bsum[t] = s[t] - v;
    if (t == 127) g_off[N] = s[127];
}

__global__ void k_scan3(int N) {
    int i = blockIdx.x * 1024 + threadIdx.x;
    if (i < N) {
        int o = g_off[i] + g_bsum[blockIdx.x];
        g_off[i] = o;
        g_cur[i] = o;
    }
}

__global__ void k_scatter(const int* __restrict__ src, const int* __restrict__ dst, int E) {
    int i = blockIdx.x * blockDim.x + threadIdx.x;
    if (i < E) {
        int d = dst[i];
        int pos = atomicAdd(&g_cur[d], 1);
        g_pes[pos] = make_int2(i, src[i]);
    }
}

// ---------------------------------------------------------------------------
__device__ __forceinline__ void load_w_rows(const float* __restrict__ W,
                                            int lane, ull* w0, ull* w1) {
    const ulonglong2* r0 = (const ulonglong2*)(W + (size_t)(2 * lane) * D);
    const ulonglong2* r1 = (const ulonglong2*)(W + (size_t)(2 * lane + 1) * D);
#pragma unroll
    for (int i = 0; i < 16; i++) {
        ulonglong2 v = r0[i]; w0[2 * i] = v.x; w0[2 * i + 1] = v.y;
        ulonglong2 u = r1[i]; w1[2 * i] = u.x; w1[2 * i + 1] = u.y;
    }
}

__device__ __forceinline__ float2 gemv2(const float* sRow, const ull* w0, const ull* w1) {
    const ulonglong2* xr = (const ulonglong2*)sRow;
    ull a00 = 0, a01 = 0, a10 = 0, a11 = 0;
#pragma unroll
    for (int i = 0; i < 16; i++) {
        ulonglong2 v = xr[i];
        a00 = fma2(v.x, w0[2 * i], a00);
        a10 = fma2(v.x, w1[2 * i], a10);
        a01 = fma2(v.y, w0[2 * i + 1], a01);
        a11 = fma2(v.y, w1[2 * i + 1], a11);
    }
    float2 f0 = unpack2(a00), f1 = unpack2(a01);
    float y0 = (f0.x + f1.x) + (f0.y + f1.y);
    f0 = unpack2(a10); f1 = unpack2(a11);
    float y1 = (f0.x + f1.x) + (f0.y + f1.y);
    return make_float2(y0, y1);
}

__device__ __forceinline__ void stage_rows(float* sXb, const float* __restrict__ G,
                                           size_t base, int nrows_total, int tid) {
#pragma unroll
    for (int i = 0; i < (WAVE * D / 4) / NT; i++) {
        int idx = tid + i * NT;
        size_t r = base + (idx >> 4);
        if (r < (size_t)nrows_total)
            cp16(sXb + (size_t)idx * 4, G + r * D + (size_t)(idx & 15) * 4);
    }
}

// ---------------------------------------------------------------------------
// g_h = node_h @ W_fc^T
__global__ __launch_bounds__(NT, 1) void k_node(
    const float* __restrict__ node_h, const float* __restrict__ W, int N) {
    extern __shared__ float smem[];
    float* sX = smem;
    int tid = threadIdx.x, lane = tid & 31, warp = tid >> 5;
    ull w0[32], w1[32];
    load_w_rows(W, lane, w0, w1);

    int nw = (N + WAVE - 1) / WAVE;
    int w = blockIdx.x;
    if (w >= nw) return;
    stage_rows(sX, node_h, (size_t)w * WAVE, N, tid);
    CP_COMMIT();

    int buf = 0;
    for (; w < nw; w += gridDim.x, buf ^= 1) {
        int wn = w + gridDim.x;
        if (wn < nw) {
            stage_rows(sX + (size_t)(buf ^ 1) * WAVE * D, node_h, (size_t)wn * WAVE, N, tid);
            CP_COMMIT();
            CP_WAIT1();
        } else {
            CP_WAIT0();
        }
        __syncthreads();
        int rbase = w * WAVE;
        const float* sXb = sX + (size_t)buf * WAVE * D;
#pragma unroll 1
        for (int r = warp; r < WAVE; r += NT / 32) {
            if (rbase + r >= N) break;
            float2 y = gemv2(sXb + (size_t)r * D, w0, w1);
            *(float2*)(g_h + (size_t)(rbase + r) * D + 2 * lane) = y;
        }
        __syncthreads();
    }
}

// ---------------------------------------------------------------------------
// Fused sorted edge pass + final output (R5 hot loop, 9 warps/SM).
#define X0   (D * LWS)
#define H0   (X0 + ENW * RING * D)
#define HN0  (H0 + ENW * RING * D)
#define OFF0 (HN0 + ENW * D)
#define EDGE_SMEM_FLOATS (OFF0 + ENW * EOFFW)

__global__ __launch_bounds__(ENT, 1) void k_edge2(
    const float* __restrict__ edge_h, const float* __restrict__ W,
    const float* __restrict__ loopW, float* __restrict__ out, int N) {
    extern __shared__ __align__(16) float smem[];
    float* sLW = smem;

    int tid = threadIdx.x, lane = tid & 31, warp = tid >> 5;
    float* sXw = smem + X0 + (size_t)warp * RING * D;
    float* sHw = smem + H0 + (size_t)warp * RING * D;
    float* sHn = smem + HN0 + (size_t)warp * D;
    int*   sOf = (int*)(smem + OFF0) + (size_t)warp * EOFFW;

    for (int i = tid; i < D * D; i += ENT) {
        int k = i >> 6, j = i & 63;
        sLW[j * LWS + k] = loopW[i];
    }
    ull w0[32], w1[32];
    load_w_rows(W, lane, w0, w1);
    __syncthreads();

    int wpg = gridDim.x * ENW;
    int gw = blockIdx.x * ENW + warp;
    int npw = (N + wpg - 1) / wpg;
    int nbeg = gw * npw;
    if (nbeg >= N) return;
    int nend = nbeg + npw; if (nend > N) nend = N;
    int nloc = nend - nbeg;

    for (int i = lane; i <= nloc; i += 32) sOf[i] = g_off[nbeg + i];
    __syncwarp();

    int kbeg = sOf[0];
    int kend_all = sOf[nloc];
    int j0 = 2 * lane;

    int n = nbeg;
    int kendn = sOf[1];
    float2 hn = *(const float2*)(g_h + (size_t)n * D + j0);
    float2 accN = make_float2(0.f, 0.f), accD = make_float2(0.f, 0.f);

    auto do_flush = [&](int node) {
        float v0, v1;
        if (accD.x > 0.f) {
            __syncwarp();
            *(float2*)(sHn + j0) = hn;
            __syncwarp();
            const ulonglong2* xr = (const ulonglong2*)sHn;
            const ulonglong2* u0 = (const ulonglong2*)(sLW + (size_t)j0 * LWS);
            const ulonglong2* u1 = (const ulonglong2*)(sLW + (size_t)(j0 + 1) * LWS);
            ull a0 = 0, a1 = 0, b0 = 0, b1 = 0;
#pragma unroll
            for (int i = 0; i < 16; i++) {
                ulonglong2 v = xr[i];
                ulonglong2 p = u0[i], q = u1[i];
                a0 = fma2(v.x, p.x, a0); a1 = fma2(v.y, p.y, a1);
                b0 = fma2(v.x, q.x, b0); b1 = fma2(v.y, q.y, b1);
            }
            float2 f0 = unpack2(a0), f1 = unpack2(a1);
            float gj0 = (f0.x + f1.x) + (f0.y + f1.y);
            f0 = unpack2(b0); f1 = unpack2(b1);
            float gj1 = (f0.x + f1.x) + (f0.y + f1.y);
            v0 = __fdividef(accN.x, accD.x) + gj0;
            v1 = __fdividef(accN.y, accD.y) + gj1;
        } else {
            v0 = hn.x; v1 = hn.y;
        }
        *(float2*)(out + (size_t)node * D + j0) =
            make_float2(fmaxf(v0, 0.f), fmaxf(v1, 0.f));
    };

    auto consume = [&](int k) {
        while (k == kendn) {
            do_flush(n);
            n++;
            hn = *(const float2*)(g_h + (size_t)n * D + j0);
            accN = make_float2(0.f, 0.f); accD = make_float2(0.f, 0.f);
            kendn = sOf[n - nbeg + 1];
        }
        int slot = k & (RING - 1);
        float2 hv = *(const float2*)(sHw + slot * D + j0);
        float2 eh = gemv2(sXw + slot * D, w0, w1);
        float ex0 = __expf(eh.x), ex1 = __expf(eh.y);
        accD.x += ex0; accD.y += ex1;
        accN.x = fmaf(ex0, hv.x + eh.x, accN.x);
        accN.y = fmaf(ex1, hv.y + eh.y, accN.y);
    };

    // pipeline prologue: 3 pair-groups covering edges kbeg .. kbeg+5
#pragma unroll
    for (int g = 0; g < 3; g++) {
#pragma unroll
        for (int h = 0; h < 2; h++) {
            int e = kbeg + 2 * g + h;
            if (e < kend_all) {
                int2 p = g_pes[e];
                int sl = e & (RING - 1);
                cp8(sXw + sl * D + j0, edge_h + (size_t)p.x * D + j0);
                cp8(sHw + sl * D + j0, g_h + (size_t)p.y * D + j0);
            }
        }
        CP_COMMIT();
    }
    int2 pa = make_int2(0, 0), pb = make_int2(0, 0);
    if (kbeg + 6 < kend_all) pa = g_pes[kbeg + 6];
    if (kbeg + 7 < kend_all) pb = g_pes[kbeg + 7];

    for (int k = kbeg; k < kend_all; k += 2) {
        // stage rows k+6, k+7 (addresses fetched last iteration)
        if (k + 6 < kend_all) {
            int sl = (k + 6) & (RING - 1);
            cp8(sXw + sl * D + j0, edge_h + (size_t)pa.x * D + j0);
            cp8(sHw + sl * D + j0, g_h + (size_t)pa.y * D + j0);
        }
        if (k + 7 < kend_all) {
            int sl = (k + 7) & (RING - 1);
            cp8(sXw + sl * D + j0, edge_h + (size_t)pb.x * D + j0);
            cp8(sHw + sl * D + j0, g_h + (size_t)pb.y * D + j0);
        }
        CP_COMMIT();
        // metadata for next iteration (edges k+8, k+9)
        if (k + 8 < kend_all) pa = g_pes[k + 8];
        if (k + 9 < kend_all) pb = g_pes[k + 9];
        CP_WAIT3();        // oldest pending group (rows k, k+1) has landed
        __syncwarp();
        consume(k);
        if (k + 1 < kend_all) consume(k + 1);
    }
    for (;;) {
        do_flush(n);
        n++;
        if (n >= nend) break;
        hn = *(const float2*)(g_h + (size_t)n * D + j0);
        accN = make_float2(0.f, 0.f); accD = make_float2(0.f, 0.f);
    }
}

// ---------------------------------------------------------------------------
extern "C" void kernel_launch(void* const* d_in, const int* in_sizes, int n_in,
                              void* d_out, int out_size) {
    const float* node_h = (const float*)d_in[0];
    const float* edge_h = (const float*)d_in[1];
    const int*   src    = (const int*)d_in[2];
    const int*   dst    = (const int*)d_in[3];
    const float* W_fc   = (const float*)d_in[4];
    const float* W_fcr  = (const float*)d_in[5];
    const float* loop_W = (const float*)d_in[6];
    float* out = (float*)d_out;

    int N = in_sizes[0] / D;
    int E = in_sizes[2];
    if (N > MAXN) N = MAXN;
    if (E > MAXE) E = MAXE;

    const int ROW_SMEM  = 2 * WAVE * D * (int)sizeof(float);
    const int EDGE_SMEM = EDGE_SMEM_FLOATS * (int)sizeof(float);  // ~59 KB
    cudaFuncSetAttribute(k_node,  cudaFuncAttributeMaxDynamicSharedMemorySize, ROW_SMEM);
    cudaFuncSetAttribute(k_edge2, cudaFuncAttributeMaxDynamicSharedMemorySize, EDGE_SMEM);

    int nb = (N + 1023) / 1024;
    k_zero<<<((N + 3) / 4 + 255) / 256, 256>>>((N + 3) / 4);
    k_node<<<152, NT, ROW_SMEM>>>(node_h, W_fc, N);
    k_hist<<<(E + 255) / 256, 256>>>(dst, E);
    k_scan1<<<nb, 1024>>>(N);
    k_scan2<<<1, 128>>>(nb, N);
    k_scan3<<<nb, 1024>>>(N);
    k_scatter<<<(E + 255) / 256, 256>>>(src, dst, E);
    k_edge2<<<EGRID, ENT, EDGE_SMEM>>>(edge_h, W_fcr, loop_W, out, N);
}

// round 15
// speedup vs baseline: 1.5811x; 1.5811x over previous
#include <cuda_runtime.h>
#include <cstdint>

#define D 64
#define MAXN 100000
#define MAXE 1600000
#define WAVE 128
#define NT 256

#define ENT 256
#define ENW 8
#define EGRID 152
#define EW 16           // edges per wave
#define LWS 68          // padded row stride for sLW
#define EOFFW 84        // per-warp offset-table entries (>= npw+1)

// Scratch (static device globals; no runtime allocation allowed)
__device__ float g_h[(size_t)MAXN * D];   // h = node_h @ W_fc^T
__device__ int   g_deg[MAXN];
__device__ int   g_off[MAXN + 1];
__device__ int   g_cur[MAXN];
__device__ int   g_bsum[128];
__device__ int2  g_pes[MAXE];             // permuted (edge_idx, src)

typedef unsigned long long ull;

__device__ __forceinline__ ull fma2(ull a, ull b, ull c) {
    ull d;
    asm("fma.rn.f32x2 %0, %1, %2, %3;" : "=l"(d) : "l"(a), "l"(b), "l"(c));
    return d;
}
__device__ __forceinline__ float2 unpack2(ull v) {
    float2 r;
    asm("mov.b64 {%0, %1}, %2;" : "=f"(r.x), "=f"(r.y) : "l"(v));
    return r;
}
__device__ __forceinline__ void cp16(void* s, const void* g) {
    unsigned a = (unsigned)__cvta_generic_to_shared(s);
    asm volatile("cp.async.cg.shared.global [%0], [%1], 16;" :: "r"(a), "l"(g));
}
#define CP_COMMIT() asm volatile("cp.async.commit_group;" ::: "memory")
#define CP_WAIT1()  asm volatile("cp.async.wait_group 1;" ::: "memory")
#define CP_WAIT0()  asm volatile("cp.async.wait_group 0;" ::: "memory")

// ---------------------------------------------------------------------------
__global__ void k_zero(int n4) {
    int i = blockIdx.x * blockDim.x + threadIdx.x;
    if (i < n4) ((int4*)g_deg)[i] = make_int4(0, 0, 0, 0);
}

__global__ void k_hist(const int* __restrict__ dst, int E) {
    int i = blockIdx.x * blockDim.x + threadIdx.x;
    if (i < E) atomicAdd(&g_deg[dst[i]], 1);
}

__global__ void k_scan1(int N) {
    __shared__ int s[1024];
    int t = threadIdx.x;
    int i = blockIdx.x * 1024 + t;
    int v = (i < N) ? g_deg[i] : 0;
    s[t] = v; __syncthreads();
#pragma unroll
    for (int d = 1; d < 1024; d <<= 1) {
        int u = (t >= d) ? s[t - d] : 0;
        __syncthreads();
        s[t] += u;
        __syncthreads();
    }
    if (i < N) g_off[i] = s[t] - v;
    if (t == 1023) g_bsum[blockIdx.x] = s[t];
}

__global__ void k_scan2(int nb, int N) {
    __shared__ int s[128];
    int t = threadIdx.x;
    int v = (t < nb) ? g_bsum[t] : 0;
    s[t] = v; __syncthreads();
#pragma unroll
    for (int d = 1; d < 128; d <<= 1) {
        int u = (t >= d) ? s[t - d] : 0;
        __syncthreads();
        s[t] += u;
        __syncthreads();
    }
    if (t < nb) g_bsum[t] = s[t] - v;
    if (t == 127) g_off[N] = s[127];
}

__global__ void k_scan3(int N) {
    int i = blockIdx.x * 1024 + threadIdx.x;
    if (i < N) {
        int o = g_off[i] + g_bsum[blockIdx.x];
        g_off[i] = o;
        g_cur[i] = o;
    }
}

__global__ void k_scatter(const int* __restrict__ src, const int* __restrict__ dst, int E) {
    int i = blockIdx.x * blockDim.x + threadIdx.x;
    if (i < E) {
        int d = dst[i];
        int pos = atomicAdd(&g_cur[d], 1);
        g_pes[pos] = make_int2(i, src[i]);
    }
}

// ---------------------------------------------------------------------------
__device__ __forceinline__ void load_w_rows(const float* __restrict__ W,
                                            int lane, ull* w0, ull* w1) {
    const ulonglong2* r0 = (const ulonglong2*)(W + (size_t)(2 * lane) * D);
    const ulonglong2* r1 = (const ulonglong2*)(W + (size_t)(2 * lane + 1) * D);
#pragma unroll
    for (int i = 0; i < 16; i++) {
        ulonglong2 v = r0[i]; w0[2 * i] = v.x; w0[2 * i + 1] = v.y;
        ulonglong2 u = r1[i]; w1[2 * i] = u.x; w1[2 * i + 1] = u.y;
    }
}

__device__ __forceinline__ float2 gemv2(const float* sRow, const ull* w0, const ull* w1) {
    const ulonglong2* xr = (const ulonglong2*)sRow;
    ull a00 = 0, a01 = 0, a10 = 0, a11 = 0;
#pragma unroll
    for (int i = 0; i < 16; i++) {
        ulonglong2 v = xr[i];
        a00 = fma2(v.x, w0[2 * i], a00);
        a10 = fma2(v.x, w1[2 * i], a10);
        a01 = fma2(v.y, w0[2 * i + 1], a01);
        a11 = fma2(v.y, w1[2 * i + 1], a11);
    }
    float2 f0 = unpack2(a00), f1 = unpack2(a01);
    float y0 = (f0.x + f1.x) + (f0.y + f1.y);
    f0 = unpack2(a10); f1 = unpack2(a11);
    float y1 = (f0.x + f1.x) + (f0.y + f1.y);
    return make_float2(y0, y1);
}

__device__ __forceinline__ void stage_rows(float* sXb, const float* __restrict__ G,
                                           size_t base, int nrows_total, int tid) {
#pragma unroll
    for (int i = 0; i < (WAVE * D / 4) / NT; i++) {
        int idx = tid + i * NT;
        size_t r = base + (idx >> 4);
        if (r < (size_t)nrows_total)
            cp16(sXb + (size_t)idx * 4, G + r * D + (size_t)(idx & 15) * 4);
    }
}

// ---------------------------------------------------------------------------
// g_h = node_h @ W_fc^T  (unchanged)
__global__ __launch_bounds__(NT, 1) void k_node(
    const float* __restrict__ node_h, const float* __restrict__ W, int N) {
    extern __shared__ float smem[];
    float* sX = smem;
    int tid = threadIdx.x, lane = tid & 31, warp = tid >> 5;
    ull w0[32], w1[32];
    load_w_rows(W, lane, w0, w1);

    int nw = (N + WAVE - 1) / WAVE;
    int w = blockIdx.x;
    if (w >= nw) return;
    stage_rows(sX, node_h, (size_t)w * WAVE, N, tid);
    CP_COMMIT();

    int buf = 0;
    for (; w < nw; w += gridDim.x, buf ^= 1) {
        int wn = w + gridDim.x;
        if (wn < nw) {
            stage_rows(sX + (size_t)(buf ^ 1) * WAVE * D, node_h, (size_t)wn * WAVE, N, tid);
            CP_COMMIT();
            CP_WAIT1();
        } else {
            CP_WAIT0();
        }
        __syncthreads();
        int rbase = w * WAVE;
        const float* sXb = sX + (size_t)buf * WAVE * D;
#pragma unroll 1
        for (int r = warp; r < WAVE; r += NT / 32) {
            if (rbase + r >= N) break;
            float2 y = gemv2(sXb + (size_t)r * D, w0, w1);
            *(float2*)(g_h + (size_t)(rbase + r) * D + 2 * lane) = y;
        }
        __syncthreads();
    }
}

// ---------------------------------------------------------------------------
// Fused sorted edge pass + final output, 16-edge waves, double-buffered.
// Dynamic smem layout (float units):
#define X0   (D * LWS)                          // sLW
#define H0   (X0 + ENW * 2 * EW * D)            // x slots: 2 waves x 16 edges
#define HN0  (H0 + ENW * 2 * EW * D)            // h slots
#define OFF0 (HN0 + ENW * D)
#define EDGE_SMEM_FLOATS (OFF0 + ENW * EOFFW)

__global__ __launch_bounds__(ENT, 1) void k_edge2(
    const float* __restrict__ edge_h, const float* __restrict__ W,
    const float* __restrict__ loopW, float* __restrict__ out, int N) {
    extern __shared__ __align__(16) float smem[];
    float* sLW = smem;

    int tid = threadIdx.x, lane = tid & 31, warp = tid >> 5;
    float* sXw = smem + X0 + (size_t)warp * 2 * EW * D;
    float* sHw = smem + H0 + (size_t)warp * 2 * EW * D;
    float* sHn = smem + HN0 + (size_t)warp * D;
    int*   sOf = (int*)(smem + OFF0) + (size_t)warp * EOFFW;

    for (int i = tid; i < D * D; i += ENT) {
        int k = i >> 6, j = i & 63;
        sLW[j * LWS + k] = loopW[i];
    }
    ull w0[32], w1[32];
    load_w_rows(W, lane, w0, w1);
    __syncthreads();

    int wpg = gridDim.x * ENW;
    int gw = blockIdx.x * ENW + warp;
    int npw = (N + wpg - 1) / wpg;
    int nbeg = gw * npw;
    if (nbeg >= N) return;
    int nend = nbeg + npw; if (nend > N) nend = N;
    int nloc = nend - nbeg;

    for (int i = lane; i <= nloc; i += 32) sOf[i] = g_off[nbeg + i];
    __syncwarp();

    int kbeg = sOf[0];
    int kend_all = sOf[nloc];
    int j0 = 2 * lane;

    int n = nbeg;
    int kendn = sOf[1];
    float2 hn = *(const float2*)(g_h + (size_t)n * D + j0);
    float2 accN = make_float2(0.f, 0.f), accD = make_float2(0.f, 0.f);

    auto do_flush = [&](int node) {
        float v0, v1;
        if (accD.x > 0.f) {
            __syncwarp();
            *(float2*)(sHn + j0) = hn;
            __syncwarp();
            const ulonglong2* xr = (const ulonglong2*)sHn;
            const ulonglong2* u0 = (const ulonglong2*)(sLW + (size_t)j0 * LWS);
            const ulonglong2* u1 = (const ulonglong2*)(sLW + (size_t)(j0 + 1) * LWS);
            ull a0 = 0, a1 = 0, b0 = 0, b1 = 0;
#pragma unroll
            for (int i = 0; i < 16; i++) {
                ulonglong2 v = xr[i];
                ulonglong2 p = u0[i], q = u1[i];
                a0 = fma2(v.x, p.x, a0); a1 = fma2(v.y, p.y, a1);
                b0 = fma2(v.x, q.x, b0); b1 = fma2(v.y, q.y, b1);
            }
            float2 f0 = unpack2(a0), f1 = unpack2(a1);
            float gj0 = (f0.x + f1.x) + (f0.y + f1.y);
            f0 = unpack2(b0); f1 = unpack2(b1);
            float gj1 = (f0.x + f1.x) + (f0.y + f1.y);
            v0 = __fdividef(accN.x, accD.x) + gj0;
            v1 = __fdividef(accN.y, accD.y) + gj1;
        } else {
            v0 = hn.x; v1 = hn.y;
        }
        *(float2*)(out + (size_t)node * D + j0) =
            make_float2(fmaxf(v0, 0.f), fmaxf(v1, 0.f));
    };

    auto consume = [&](int k, const float* sXs, const float* sHs, int e) {
        while (k == kendn) {
            do_flush(n);
            n++;
            hn = *(const float2*)(g_h + (size_t)n * D + j0);
            accN = make_float2(0.f, 0.f); accD = make_float2(0.f, 0.f);
            kendn = sOf[n - nbeg + 1];
        }
        float2 hv = *(const float2*)(sHs + e * D + j0);
        float2 eh = gemv2(sXs + e * D, w0, w1);
        float ex0 = __expf(eh.x), ex1 = __expf(eh.y);
        accD.x += ex0; accD.y += ex1;
        accN.x = fmaf(ex0, hv.x + eh.x, accN.x);
        accN.y = fmaf(ex1, hv.y + eh.y, accN.y);
    };

    // Stage one 16-edge wave into slot s using per-lane pes register.
    // Lane l holds pes for edge (base + l), l < EW. Each cp16 instruction
    // copies 2 rows (lane>>4 selects row parity, lane&15 selects 4B x4 chunk).
    auto stage_wave = [&](int base, int slot, int2 pesLane) {
        float* sx = sXw + (size_t)slot * EW * D;
        float* sh = sHw + (size_t)slot * EW * D;
        int chunk = lane & 15;                 // 16B chunk index within row
        int rpar = lane >> 4;                  // row parity
#pragma unroll
        for (int i = 0; i < 8; i++) {
            int r = 2 * i + rpar;              // row 0..15
            int ex = __shfl_sync(0xffffffffu, pesLane.x, r);
            int sx_ = __shfl_sync(0xffffffffu, pesLane.y, r);
            if (base + r < kend_all) {
                cp16(sx + (size_t)r * D + chunk * 4,
                     edge_h + (size_t)ex * D + chunk * 4);
                cp16(sh + (size_t)r * D + chunk * 4,
                     g_h + (size_t)sx_ * D + chunk * 4);
            }
        }
    };
    auto load_pes = [&](int base) -> int2 {
        int idx = base + (lane & 15);
        if (idx >= kend_all) idx = kend_all - 1;
        return g_pes[idx];
    };

    int nwv = (kend_all - kbeg + EW - 1) / EW;
    if (nwv > 0) {
        int2 pes0 = load_pes(kbeg);
        stage_wave(kbeg, 0, pes0);
        CP_COMMIT();
        int2 pesN = (nwv > 1) ? load_pes(kbeg + EW) : make_int2(0, 0);

#pragma unroll 1
        for (int w = 0; w < nwv; w++) {
            int base = kbeg + w * EW;
            if (w + 1 < nwv) {
                stage_wave(base + EW, (w + 1) & 1, pesN);
                CP_COMMIT();
                if (w + 2 < nwv) pesN = load_pes(base + 2 * EW);
                CP_WAIT1();
            } else {
                CP_WAIT0();
            }
            __syncwarp();
            const float* sXs = sXw + (size_t)(w & 1) * EW * D;
            const float* sHs = sHw + (size_t)(w & 1) * EW * D;
            int cnt = kend_all - base; if (cnt > EW) cnt = EW;
#pragma unroll 1
            for (int e = 0; e < cnt; e++)
                consume(base + e, sXs, sHs, e);
            __syncwarp();
        }
    }
    // tail: flush current node, then remaining (empty) nodes
    for (;;) {
        do_flush(n);
        n++;
        if (n >= nend) break;
        hn = *(const float2*)(g_h + (size_t)n * D + j0);
        accN = make_float2(0.f, 0.f); accD = make_float2(0.f, 0.f);
    }
}

// ---------------------------------------------------------------------------
extern "C" void kernel_launch(void* const* d_in, const int* in_sizes, int n_in,
                              void* d_out, int out_size) {
    const float* node_h = (const float*)d_in[0];
    const float* edge_h = (const float*)d_in[1];
    const int*   src    = (const int*)d_in[2];
    const int*   dst    = (const int*)d_in[3];
    const float* W_fc   = (const float*)d_in[4];
    const float* W_fcr  = (const float*)d_in[5];
    const float* loop_W = (const float*)d_in[6];
    float* out = (float*)d_out;

    int N = in_sizes[0] / D;
    int E = in_sizes[2];
    if (N > MAXN) N = MAXN;
    if (E > MAXE) E = MAXE;

    const int ROW_SMEM  = 2 * WAVE * D * (int)sizeof(float);
    const int EDGE_SMEM = EDGE_SMEM_FLOATS * (int)sizeof(float);  // ~151 KB
    cudaFuncSetAttribute(k_node,  cudaFuncAttributeMaxDynamicSharedMemorySize, ROW_SMEM);
    cudaFuncSetAttribute(k_edge2, cudaFuncAttributeMaxDynamicSharedMemorySize, EDGE_SMEM);

    int nb = (N + 1023) / 1024;
    k_zero<<<((N + 3) / 4 + 255) / 256, 256>>>((N + 3) / 4);
    k_node<<<152, NT, ROW_SMEM>>>(node_h, W_fc, N);
    k_hist<<<(E + 255) / 256, 256>>>(dst, E);
    k_scan1<<<nb, 1024>>>(N);
    k_scan2<<<1, 128>>>(nb, N);
    k_scan3<<<nb, 1024>>>(N);
    k_scatter<<<(E + 255) / 256, 256>>>(src, dst, E);
    k_edge2<<<EGRID, ENT, EDGE_SMEM>>>(edge_h, W_fcr, loop_W, out, N);
}